// round 17
// baseline (speedup 1.0000x reference)
#include <cuda_runtime.h>
#include <cuda_fp16.h>

#define SH 16
#define SW 16
#define SL 8
#define NCOEF 12
#define GRID_ELEMS (SH * SW * SL * NCOEF)        // 24576 halfs per copy
// Copy B at +GRID_ELEMS+20 halfs: odd-z0 records are 16B-aligned there; the
// +10-word rotation keeps the two copies' record lattices on disjoint quads.
#define COPY_B_OFF (GRID_ELEMS + 20)
#define SMEM_HALFS (COPY_B_OFF + GRID_ELEMS)
#define SMEM_BYTES (SMEM_HALFS * 2)              // 98344 B -> 2 CTAs/SM

__device__ __forceinline__ __half2 as_h2(unsigned int u) {
    return *reinterpret_cast<__half2*>(&u);
}

__device__ __forceinline__ void process_pixel(
    const __half* __restrict__ sg,
    float r, float g, float b, float cxv, float cyv,
    float& o0, float& o1, float& o2)
{
    const float guide = 0.2126f * r + 0.7152f * g + 0.0722f * b;
    const float gx = fminf(fmaxf(cxv * (float)(SW - 1), 0.0f), (float)SW - 1.001f);
    const float gy = fminf(fmaxf(cyv * (float)(SH - 1), 0.0f), (float)SH - 1.001f);
    const float gcl = fminf(fmaxf(guide, 0.0f), 1.0f);
    const float gz = fminf(fmaxf(gcl * (float)(SL - 1), 0.0f), (float)SL - 1.001f);

    const int x0 = (int)gx;
    const int y0 = (int)gy;
    const int z0 = (int)gz;
    const float fx = gx - (float)x0;
    const float fy = gy - (float)y0;
    const float fz = gz - (float)z0;
    const float wx0 = 1.0f - fx, wy0 = 1.0f - fy, wz0 = 1.0f - fz;

    const __half* base = sg + ((z0 & 1) ? COPY_B_OFF : 0)
                       + (((y0 << 4) + x0) * SL + z0) * NCOEF;

    __half2 acc0 = __float2half2_rn(0.f), acc1 = acc0, acc2 = acc0;
    __half2 acc3 = acc0, acc4 = acc0, acc5 = acc0;

    #pragma unroll
    for (int dy = 0; dy < 2; ++dy) {
        const float wyv = dy ? fy : wy0;
        #pragma unroll
        for (int dx = 0; dx < 2; ++dx) {
            const float wxy = wyv * (dx ? fx : wx0);
            // 48 B record: z0's 12 halfs then z1's 12 halfs, 16B-aligned.
            const uint4* p4 = reinterpret_cast<const uint4*>(
                base + dy * (SW * SL * NCOEF) + dx * (SL * NCOEF));
            const uint4 q0 = p4[0];
            const uint4 q1 = p4[1];
            const uint4 q2 = p4[2];

            const __half2 w0 = __float2half2_rn(wxy * wz0);
            const __half2 w1 = __float2half2_rn(wxy * fz);

            acc0 = __hfma2(w0, as_h2(q0.x), acc0);
            acc1 = __hfma2(w0, as_h2(q0.y), acc1);
            acc2 = __hfma2(w0, as_h2(q0.z), acc2);
            acc3 = __hfma2(w0, as_h2(q0.w), acc3);
            acc4 = __hfma2(w0, as_h2(q1.x), acc4);
            acc5 = __hfma2(w0, as_h2(q1.y), acc5);

            acc0 = __hfma2(w1, as_h2(q1.z), acc0);
            acc1 = __hfma2(w1, as_h2(q1.w), acc1);
            acc2 = __hfma2(w1, as_h2(q2.x), acc2);
            acc3 = __hfma2(w1, as_h2(q2.y), acc3);
            acc4 = __hfma2(w1, as_h2(q2.z), acc4);
            acc5 = __hfma2(w1, as_h2(q2.w), acc5);
        }
    }

    const float2 f0 = __half22float2(acc0);
    const float2 f1 = __half22float2(acc1);
    const float2 f2 = __half22float2(acc2);
    const float2 f3 = __half22float2(acc3);
    const float2 f4 = __half22float2(acc4);
    const float2 f5 = __half22float2(acc5);

    o0 = f0.x * r + f0.y * g + f1.x * b + f1.y;
    o1 = f2.x * r + f2.y * g + f3.x * b + f3.y;
    o2 = f4.x * r + f4.y * g + f5.x * b + f5.y;
}

__global__ void __launch_bounds__(384, 2)
bilateral_grid_u3_kernel(const float* __restrict__ pixels,
                         const float* __restrict__ coords,
                         const float* __restrict__ grid,
                         float* __restrict__ out,
                         int N)
{
    extern __shared__ __half sg[];

    // Convert fp32 grid -> fp16, write BOTH copies.
    {
        const float2* g2 = reinterpret_cast<const float2*>(grid);
        __half2* a2 = reinterpret_cast<__half2*>(sg);
        __half2* b2 = reinterpret_cast<__half2*>(sg + COPY_B_OFF);
        #pragma unroll 4
        for (int i = threadIdx.x; i < GRID_ELEMS / 2; i += 384) {
            const __half2 v = __float22half2_rn(g2[i]);
            a2[i] = v;
            b2[i] = v;
        }
    }
    __syncthreads();

    const int stride = gridDim.x * blockDim.x;
    const int tid0 = blockIdx.x * blockDim.x + threadIdx.x;

    // Unroll x3 with front-batched globals: iterations k+1 and k+2's LDGs
    // issue inside iteration k's LDS-wait shadow (deeper cross-iteration MLP).
    int i = tid0;
    for (; i + 2 * stride < N; i += 3 * stride) {
        const int j = i + stride;
        const int k = j + stride;

        const float r0 = pixels[3 * i + 0];
        const float g0 = pixels[3 * i + 1];
        const float b0 = pixels[3 * i + 2];
        const float2 c0 = reinterpret_cast<const float2*>(coords)[i];
        const float r1 = pixels[3 * j + 0];
        const float g1 = pixels[3 * j + 1];
        const float b1 = pixels[3 * j + 2];
        const float2 c1 = reinterpret_cast<const float2*>(coords)[j];
        const float r2 = pixels[3 * k + 0];
        const float g2 = pixels[3 * k + 1];
        const float b2 = pixels[3 * k + 2];
        const float2 c2 = reinterpret_cast<const float2*>(coords)[k];

        float o0, o1, o2;
        process_pixel(sg, r0, g0, b0, c0.x, c0.y, o0, o1, o2);
        out[3 * i + 0] = o0;
        out[3 * i + 1] = o1;
        out[3 * i + 2] = o2;

        float p0, p1, p2;
        process_pixel(sg, r1, g1, b1, c1.x, c1.y, p0, p1, p2);
        out[3 * j + 0] = p0;
        out[3 * j + 1] = p1;
        out[3 * j + 2] = p2;

        float q0, q1, q2;
        process_pixel(sg, r2, g2, b2, c2.x, c2.y, q0, q1, q2);
        out[3 * k + 0] = q0;
        out[3 * k + 1] = q1;
        out[3 * k + 2] = q2;
    }
    for (; i < N; i += stride) {
        const float r = pixels[3 * i + 0];
        const float g = pixels[3 * i + 1];
        const float b = pixels[3 * i + 2];
        const float2 c = reinterpret_cast<const float2*>(coords)[i];
        float o0, o1, o2;
        process_pixel(sg, r, g, b, c.x, c.y, o0, o1, o2);
        out[3 * i + 0] = o0;
        out[3 * i + 1] = o1;
        out[3 * i + 2] = o2;
    }
}

extern "C" void kernel_launch(void* const* d_in, const int* in_sizes, int n_in,
                              void* d_out, int out_size)
{
    const float* pixels = (const float*)d_in[0];   // (B,H,W,3) f32
    const float* coords = (const float*)d_in[1];   // (B,H,W,2) f32
    const float* grid   = (const float*)d_in[2];   // (16,16,8,12) f32
    float* out = (float*)d_out;

    const int N = in_sizes[0] / 3;

    cudaFuncSetAttribute(bilateral_grid_u3_kernel,
                         cudaFuncAttributeMaxDynamicSharedMemorySize, SMEM_BYTES);

    // 2 CTAs/SM x 152 SMs, 384 threads -> 24 warps/SM, reg cap 85.
    const int blocks = 304;
    bilateral_grid_u3_kernel<<<blocks, 384, SMEM_BYTES>>>(pixels, coords, grid, out, N);
}